// round 9
// baseline (speedup 1.0000x reference)
#include <cuda_runtime.h>
#include <cstdint>
#include <math.h>

#define IN_D  64
#define H_D   256
#define B_D   128
#define T_D   512
#define GRID  128
#define BLOCK 512

typedef unsigned long long u64;

// ---------------- device globals ----------------
__device__ float h1_buf[2][B_D * H_D];
__device__ float h2_buf[2][B_D * H_D];
__device__ unsigned bar_cnt4[4][32];
__device__ unsigned bar_gen4[4][32];
__device__ unsigned gbar_cnt_all;
__device__ unsigned gbar_gen_all;

// ---------------- smem layout ----------------
// wA : [32 c][162 k2] u64 = 41472   (layer1, K=320 -> 160 k-pairs)
// wB : [32 c][258 k2] u64 = 66048   (layer2, K=512 -> 256 k-pairs)
// u  : [32 b][145 f4]      = 74240  merged staging: rows 0..15 = x(i),
//                                   16..79 = h1(i-1), 80..143 = h2(i-2)
//                                   stride 145 f4 -> slot (bq+k)%8 conflict-free
// part:[8 sl][32 b][40 c] f32 = 40960
#define WA_S2 81     /* wA row stride in ulonglong2 (16B) units */
#define WB_S2 129    /* wB row stride */
#define U_S2  145    /* u  row stride in ulonglong2 units (= float4 units) */
#define OFF_WA 0
#define OFF_WB 41472
#define OFF_U  107520
#define OFF_P  181760
#define OFF_BA 222720
#define OFF_BB 222848
#define SMEM_BYTES 222976

// ---------------- asm helpers ----------------
__device__ __forceinline__ unsigned ld_acq(const unsigned* p) {
    unsigned v;
    asm volatile("ld.acquire.gpu.u32 %0, [%1];" : "=r"(v) : "l"(p) : "memory");
    return v;
}
__device__ __forceinline__ void st_rel(unsigned* p, unsigned v) {
    asm volatile("st.release.gpu.u32 [%0], %1;" :: "l"(p), "r"(v) : "memory");
}
__device__ __forceinline__ unsigned atom_add_acqrel(unsigned* p) {
    unsigned v;
    asm volatile("atom.acq_rel.gpu.global.add.u32 %0, [%1], 1;" : "=r"(v) : "l"(p) : "memory");
    return v;
}
__device__ __forceinline__ u64 fma2(u64 a, u64 b, u64 c) {
    u64 d;
    asm("fma.rn.f32x2 %0, %1, %2, %3;" : "=l"(d) : "l"(a), "l"(b), "l"(c));
    return d;
}
__device__ __forceinline__ float2 unpack2(u64 v) {
    float2 r; asm("mov.b64 {%0,%1}, %2;" : "=f"(r.x), "=f"(r.y) : "l"(v)); return r;
}
__device__ __forceinline__ float tanh_fast(float x) {
    float r;
    asm("tanh.approx.f32 %0, %1;" : "=f"(r) : "f"(x));
    return r;
}

// ---------------- grid barrier ----------------
__device__ __forceinline__ void gbar(unsigned* cnt, unsigned* gen,
                                     unsigned nctas, unsigned target) {
    __syncthreads();
    if (threadIdx.x == 0) {
        unsigned prev = atom_add_acqrel(cnt);
        if (prev == nctas - 1) {
            *cnt = 0;
            st_rel(gen, target);
        } else {
            while ((int)(ld_acq(gen) - target) < 0) { }
        }
    }
    __syncthreads();
}

// ---------------- register-tiled GEMM ----------------
// 16 warps = 8 k-slices x 2 c-halves. Lanes (bq 0..7, cq 0..3).
// Thread tile 4b x 4c: b in {bq+8r}, c in {cg*16 + 2cq + {0,1,8,9}}.
// u rows stride U_S2 ull2, UOFF selects [x|h1] (0) or [h1|h2] (16).
template<int K2S, int WS2, int UOFF>
__device__ __forceinline__ void gemm_tile(const u64* __restrict__ wsm,
                                          const u64* __restrict__ usm,
                                          float* __restrict__ part,
                                          int sl, int cg, int lane) {
    const int bq = lane & 7, cq = (lane >> 3) & 3;
    const int k2h = (sl * K2S) >> 1;   // slice base in ulonglong2 units
    const ulonglong2* up = (const ulonglong2*)usm + bq * U_S2 + UOFF + k2h;
    const ulonglong2* wp = (const ulonglong2*)wsm + (cg * 16 + 2 * cq) * WS2 + k2h;

    u64 acc[4][4];
#pragma unroll
    for (int r = 0; r < 4; ++r)
#pragma unroll
        for (int j = 0; j < 4; ++j) acc[r][j] = 0;

#pragma unroll 2
    for (int k = 0; k < K2S / 2; ++k) {
        ulonglong2 uf0 = up[k];
        ulonglong2 uf1 = up[k +  8 * U_S2];
        ulonglong2 uf2 = up[k + 16 * U_S2];
        ulonglong2 uf3 = up[k + 24 * U_S2];
        ulonglong2 wf0 = wp[k];
        ulonglong2 wf1 = wp[k + WS2];
        ulonglong2 wf2 = wp[k + 8 * WS2];
        ulonglong2 wf3 = wp[k + 9 * WS2];
#pragma unroll
        for (int r = 0; r < 4; ++r) {
            ulonglong2 uv = (r == 0) ? uf0 : (r == 1) ? uf1 : (r == 2) ? uf2 : uf3;
            acc[r][0] = fma2(uv.x, wf0.x, acc[r][0]);
            acc[r][0] = fma2(uv.y, wf0.y, acc[r][0]);
            acc[r][1] = fma2(uv.x, wf1.x, acc[r][1]);
            acc[r][1] = fma2(uv.y, wf1.y, acc[r][1]);
            acc[r][2] = fma2(uv.x, wf2.x, acc[r][2]);
            acc[r][2] = fma2(uv.y, wf2.y, acc[r][2]);
            acc[r][3] = fma2(uv.x, wf3.x, acc[r][3]);
            acc[r][3] = fma2(uv.y, wf3.y, acc[r][3]);
        }
    }

    float* pp = part + sl * 1280 + bq * 40 + cg * 16 + 2 * cq;
#pragma unroll
    for (int r = 0; r < 4; ++r) {
        float2 a = unpack2(acc[r][0]);
        float2 b = unpack2(acc[r][1]);
        float2 c = unpack2(acc[r][2]);
        float2 d = unpack2(acc[r][3]);
        *(float2*)(pp + 320 * r)     = make_float2(a.x + a.y, b.x + b.y);
        *(float2*)(pp + 320 * r + 8) = make_float2(c.x + c.y, d.x + d.y);
    }
}

// ---------------- fused partial-reduce + sLSTM cell update ----------------
__device__ __forceinline__ float cell_fused(const float* __restrict__ part,
                                            const float* __restrict__ bias,
                                            int be, int je,
                                            float& c, float& m, float& n) {
    float g4[4];
#pragma unroll
    for (int g = 0; g < 4; ++g) {
        const float* p = part + be * 40 + g * 8 + je;
        float s = bias[g * 8 + je];
#pragma unroll
        for (int sl = 0; sl < 8; ++sl) s += p[sl * 1280];
        g4[g] = s;
    }
    float ig = g4[0], fg = g4[1], zg = g4[2], og = g4[3];
    float z  = tanh_fast(zg);
    float o  = __fdividef(1.0f, 1.0f + __expf(-og));
    float mt = fmaxf(fg + m, ig);
    float it = __expf(ig - mt);
    float ft = __expf(fg + m - mt);
    c = ft * c + it * z;
    n = ft * n + it;
    m = mt;
    return o * __fdividef(c, n);
}

// ---------------- main persistent kernel ----------------
__global__ void __launch_bounds__(BLOCK, 1)
slstm_kernel(const float* __restrict__ x,
             const float* __restrict__ Wxh1, const float* __restrict__ bxh1,
             const float* __restrict__ Whh1, const float* __restrict__ bhh1,
             const float* __restrict__ Wxh2, const float* __restrict__ bxh2,
             const float* __restrict__ Whh2, const float* __restrict__ bhh2,
             const float* __restrict__ W1, const float* __restrict__ b1,
             const float* __restrict__ W2, const float* __restrict__ b2,
             const float* __restrict__ W3, const float* __restrict__ b3,
             float* __restrict__ out) {
    extern __shared__ char smem[];
    u64*    wA    = (u64*)(smem + OFF_WA);
    u64*    wB    = (u64*)(smem + OFF_WB);
    u64*    usm   = (u64*)(smem + OFF_U);
    float4* u4f   = (float4*)(smem + OFF_U);
    float*  part  = (float*)(smem + OFF_P);
    float*  biasA = (float*)(smem + OFF_BA);
    float*  biasB = (float*)(smem + OFF_BB);

    const int tid  = threadIdx.x;
    const int warp = tid >> 5, lane = tid & 31;
    const int sl = warp >> 1, cg = warp & 1;
    const int bgroup = blockIdx.x >> 5;   // 0..3  (32 batch rows each)
    const int jgroup = blockIdx.x & 31;   // 0..31 (8 hidden idx each)

    unsigned* my_cnt = &bar_cnt4[bgroup][0];
    unsigned* my_gen = &bar_gen4[bgroup][0];
    const unsigned base_g   = ld_acq(my_gen);
    const unsigned base_all = ld_acq(&gbar_gen_all);

    // staging thread mapping: sb = batch row (0..31), sq = 0..15
    const int sb = tid >> 4, sq = tid & 15;
    const int bglobs = bgroup * 32 + sb;
    const float4 zero4 = make_float4(0.f, 0.f, 0.f, 0.f);

    // prefetch x(0) while weights stage
    float4 xv = *(const float4*)(x + (bglobs * T_D + 0) * IN_D + sq * 4);

    // ---- stage weights + biases (once) ----
    {
        float2* wAf = (float2*)wA;
        for (int s = tid; s < 32 * 160; s += BLOCK) {
            int c = s / 160, k2 = s - c * 160;
            int col = (c >> 3) * 256 + jgroup * 8 + (c & 7);
            int k0 = 2 * k2;
            float2 v;
            if (k0 < IN_D) v = *(const float2*)(Wxh1 + col * IN_D + k0);
            else           v = *(const float2*)(Whh1 + col * H_D + (k0 - IN_D));
            wAf[c * 162 + k2] = v;
        }
        float2* wBf = (float2*)wB;
        for (int s = tid; s < 32 * 256; s += BLOCK) {
            int c = s >> 8, k2 = s & 255;
            int col = (c >> 3) * 256 + jgroup * 8 + (c & 7);
            int k0 = 2 * k2;
            float2 v;
            if (k0 < H_D) v = *(const float2*)(Wxh2 + col * H_D + k0);
            else          v = *(const float2*)(Whh2 + col * H_D + (k0 - H_D));
            wBf[c * 258 + k2] = v;
        }
    }
    if (tid < 32) {
        int col = (tid >> 3) * 256 + jgroup * 8 + (tid & 7);
        biasA[tid] = bxh1[col] + bhh1[col];
        biasB[tid] = bxh2[col] + bhh2[col];
    }
    __syncthreads();

    // per-thread cell state (tid<256)
    float c1 = 0.f, m1 = 0.f, n1 = 0.f;
    float c2 = 0.f, m2 = 0.f, n2 = 0.f;
    const int be = tid >> 3, je = tid & 7;
    const int bglob_e = bgroup * 32 + be;
    const int jglob   = jgroup * 8 + je;

    // interval i: computes h1(i) (layer1 at time i) and h2(i-1) (layer2 at i-1)
    for (int i = 0; i <= T_D; ++i) {
        const float* h1old  = h1_buf[(i + 1) & 1];  // h1(i-1)
        float*       h1cur  = h1_buf[i & 1];        // h1(i)
        const float* h2old2 = h2_buf[i & 1];        // h2(i-2)
        float*       h2cur  = h2_buf[(i + 1) & 1];  // h2(i-1)

        // ---- merged staging: rows 0..15 x(i) | 16..79 h1(i-1) | 80..143 h2(i-2) ----
        if (i < T_D) u4f[sb * U_S2 + sq] = xv;
        {
            float4 av[4], bv[4];
#pragma unroll
            for (int j = 0; j < 4; ++j)
                av[j] = (i == 0) ? zero4
                      : __ldcg((const float4*)(h1old + bglobs * H_D + (sq + 16 * j) * 4));
#pragma unroll
            for (int j = 0; j < 4; ++j)
                bv[j] = (i <= 1) ? zero4
                      : __ldcg((const float4*)(h2old2 + bglobs * H_D + (sq + 16 * j) * 4));
#pragma unroll
            for (int j = 0; j < 4; ++j) u4f[sb * U_S2 + 16 + sq + 16 * j] = av[j];
#pragma unroll
            for (int j = 0; j < 4; ++j) u4f[sb * U_S2 + 80 + sq + 16 * j] = bv[j];
        }
        __syncthreads();

        // ---- layer 1 at time i ----
        if (i < T_D) {
            gemm_tile<20, WA_S2, 0>(wA, usm, part, sl, cg, lane);
            __syncthreads();
            if (tid < 256) {
                float h1v = cell_fused(part, biasA, be, je, c1, m1, n1);
                h1cur[bglob_e * H_D + jglob] = h1v;
            }
        }

        // ---- layer 2 at time i-1 ----
        if (i > 0) {
            __syncthreads();   // cellA partial reads done before gemmB overwrites
            gemm_tile<32, WB_S2, 16>(wB, usm, part, sl, cg, lane);
            __syncthreads();
            if (tid < 256) {
                float h2v = cell_fused(part, biasB, be, je, c2, m2, n2);
                h2cur[bglob_e * H_D + jglob] = h2v;
            }
        }

        // prefetch next x (overlaps barrier spin)
        if (i + 1 < T_D)
            xv = *(const float4*)(x + (bglobs * T_D + (i + 1)) * IN_D + sq * 4);

        if (i < T_D)
            gbar(my_cnt, my_gen, 32u, base_g + (unsigned)i + 1u);
    }

    // all 128 CTAs must see final h2 before the head MLP
    gbar(&gbar_cnt_all, &gbar_gen_all, (unsigned)GRID, base_all + 1u);

    // ---- head MLP: one batch row per CTA ----
    {
        const float* h2fin = h2_buf[(T_D - 1) & 1];
        int b = blockIdx.x;
        float* hb = (float*)(smem + OFF_U);
        float* o1 = hb + 256;
        float* o2 = o1 + 128;
        float* pr = o2 + 64;
        for (int i = tid; i < H_D; i += BLOCK) hb[i] = __ldcg(h2fin + b * H_D + i);
        __syncthreads();
        if (tid < 128) {
            const float* w = W1 + tid * H_D;
            float s = b1[tid];
#pragma unroll 4
            for (int k = 0; k < H_D; k += 4) {
                float4 hv = *(const float4*)(hb + k);
                float4 wv = *(const float4*)(w + k);
                s += hv.x * wv.x + hv.y * wv.y + hv.z * wv.z + hv.w * wv.w;
            }
            o1[tid] = fmaxf(s, 0.f);
        }
        __syncthreads();
        if (tid < 64) {
            const float* w = W2 + tid * 128;
            float s = b2[tid];
#pragma unroll 4
            for (int k = 0; k < 128; ++k) s += o1[k] * w[k];
            o2[tid] = fmaxf(s, 0.f);
        }
        __syncthreads();
        if (tid < 64) pr[tid] = o2[tid] * W3[tid];
        __syncthreads();
        if (tid == 0) {
            float s = b3[0];
            for (int k = 0; k < 64; ++k) s += pr[k];
            out[b] = s;
        }
    }
}

extern "C" void kernel_launch(void* const* d_in, const int* in_sizes, int n_in,
                              void* d_out, int out_size) {
    const float* x    = (const float*)d_in[0];
    const float* Wxh1 = (const float*)d_in[1];
    const float* bxh1 = (const float*)d_in[2];
    const float* Whh1 = (const float*)d_in[3];
    const float* bhh1 = (const float*)d_in[4];
    const float* Wxh2 = (const float*)d_in[5];
    const float* bxh2 = (const float*)d_in[6];
    const float* Whh2 = (const float*)d_in[7];
    const float* bhh2 = (const float*)d_in[8];
    const float* W1   = (const float*)d_in[9];
    const float* b1   = (const float*)d_in[10];
    const float* W2   = (const float*)d_in[11];
    const float* b2   = (const float*)d_in[12];
    const float* W3   = (const float*)d_in[13];
    const float* b3   = (const float*)d_in[14];

    cudaFuncSetAttribute(slstm_kernel,
                         cudaFuncAttributeMaxDynamicSharedMemorySize, SMEM_BYTES);
    slstm_kernel<<<GRID, BLOCK, SMEM_BYTES>>>(x, Wxh1, bxh1, Whh1, bhh1,
                                              Wxh2, bxh2, Whh2, bhh2,
                                              W1, b1, W2, b2, W3, b3,
                                              (float*)d_out);
}

// round 10
// speedup vs baseline: 1.0615x; 1.0615x over previous
#include <cuda_runtime.h>
#include <cstdint>
#include <math.h>

#define IN_D  64
#define H_D   256
#define B_D   128
#define T_D   512
#define GRID  128
#define BLOCK 512

typedef unsigned long long u64;

// ---------------- device globals ----------------
__device__ float h1_buf[2][B_D * H_D];
__device__ float h2_buf[2][B_D * H_D];
__device__ unsigned bar_flag[4][32][32];   // [bgroup][cta][pad] one flag per 128B line
__device__ unsigned gbar_cnt_all;
__device__ unsigned gbar_gen_all;

// ---------------- smem layout ----------------
// wA : [32 c][162 k2] u64 = 41472  (layer1, k-order = [h1(256) | x(64)])
// wB : [32 c][258 k2] u64 = 66048  (layer2, k-order = [h1(256) | h2(256)])
// u  : [32 b][129 f4]     = 66048  rows 0..63 h1, 64..79 x (phase A) / 64..127 h2 (phase B)
// part:[8 sl][32 b][40 c] f32 = 40960
#define WA_S2 81     /* wA row stride in ulonglong2 (16B) units */
#define WB_S2 129    /* wB row stride */
#define U_S2  129    /* u row stride in float4/ulonglong2 units */
#define OFF_WA 0
#define OFF_WB 41472
#define OFF_U  107520
#define OFF_P  173568
#define OFF_BA 214528
#define OFF_BB 214656
#define SMEM_BYTES 214784

// ---------------- asm helpers ----------------
__device__ __forceinline__ unsigned ld_acq(const unsigned* p) {
    unsigned v;
    asm volatile("ld.acquire.gpu.u32 %0, [%1];" : "=r"(v) : "l"(p) : "memory");
    return v;
}
__device__ __forceinline__ void st_rel(unsigned* p, unsigned v) {
    asm volatile("st.release.gpu.u32 [%0], %1;" :: "l"(p), "r"(v) : "memory");
}
__device__ __forceinline__ unsigned atom_add_acqrel(unsigned* p) {
    unsigned v;
    asm volatile("atom.acq_rel.gpu.global.add.u32 %0, [%1], 1;" : "=r"(v) : "l"(p) : "memory");
    return v;
}
__device__ __forceinline__ u64 fma2(u64 a, u64 b, u64 c) {
    u64 d;
    asm("fma.rn.f32x2 %0, %1, %2, %3;" : "=l"(d) : "l"(a), "l"(b), "l"(c));
    return d;
}
__device__ __forceinline__ float2 unpack2(u64 v) {
    float2 r; asm("mov.b64 {%0,%1}, %2;" : "=f"(r.x), "=f"(r.y) : "l"(v)); return r;
}
__device__ __forceinline__ float tanh_fast(float x) {
    float r;
    asm("tanh.approx.f32 %0, %1;" : "=f"(r) : "f"(x));
    return r;
}

// ---------------- flag-based group barrier (32 CTAs) ----------------
// arrival: one release store per CTA; wait: warp0 lane L polls peer L's flag.
__device__ __forceinline__ void gbar_flags(unsigned bgroup, unsigned myid,
                                           int warp, int lane, unsigned target) {
    __syncthreads();
    if (threadIdx.x == 0) {
        __threadfence();
        st_rel(&bar_flag[bgroup][myid][0], target);
    }
    if (warp == 0) {
        unsigned* f = &bar_flag[bgroup][lane][0];
        while ((int)(ld_acq(f) - target) < 0) { }
    }
    __syncthreads();
}

// ---------------- atomic chip barrier (used once) ----------------
__device__ __forceinline__ void gbar_all(unsigned target) {
    __syncthreads();
    if (threadIdx.x == 0) {
        unsigned prev = atom_add_acqrel(&gbar_cnt_all);
        if (prev == GRID - 1) {
            gbar_cnt_all = 0;
            st_rel(&gbar_gen_all, target);
        } else {
            while ((int)(ld_acq(&gbar_gen_all) - target) < 0) { }
        }
    }
    __syncthreads();
}

// ---------------- register-tiled GEMM ----------------
// 16 warps = 8 k-slices x 2 c-halves. Lanes (bq 0..7, cq 0..3).
// Thread tile 4b x 4c: b in {bq+8r}, c in {cg*16 + 2cq + {0,1,8,9}}.
template<int K2S, int WS2>
__device__ __forceinline__ void gemm_tile(const u64* __restrict__ wsm,
                                          const u64* __restrict__ usm,
                                          float* __restrict__ part,
                                          int sl, int cg, int lane) {
    const int bq = lane & 7, cq = (lane >> 3) & 3;
    const int k2h = (sl * K2S) >> 1;   // slice base in ulonglong2 units
    const ulonglong2* up = (const ulonglong2*)usm + bq * U_S2 + k2h;
    const ulonglong2* wp = (const ulonglong2*)wsm + (cg * 16 + 2 * cq) * WS2 + k2h;

    u64 acc[4][4];
#pragma unroll
    for (int r = 0; r < 4; ++r)
#pragma unroll
        for (int j = 0; j < 4; ++j) acc[r][j] = 0;

#pragma unroll 2
    for (int k = 0; k < K2S / 2; ++k) {
        ulonglong2 uf0 = up[k];
        ulonglong2 uf1 = up[k +  8 * U_S2];
        ulonglong2 uf2 = up[k + 16 * U_S2];
        ulonglong2 uf3 = up[k + 24 * U_S2];
        ulonglong2 wf0 = wp[k];
        ulonglong2 wf1 = wp[k + WS2];
        ulonglong2 wf2 = wp[k + 8 * WS2];
        ulonglong2 wf3 = wp[k + 9 * WS2];
#pragma unroll
        for (int r = 0; r < 4; ++r) {
            ulonglong2 uv = (r == 0) ? uf0 : (r == 1) ? uf1 : (r == 2) ? uf2 : uf3;
            acc[r][0] = fma2(uv.x, wf0.x, acc[r][0]);
            acc[r][0] = fma2(uv.y, wf0.y, acc[r][0]);
            acc[r][1] = fma2(uv.x, wf1.x, acc[r][1]);
            acc[r][1] = fma2(uv.y, wf1.y, acc[r][1]);
            acc[r][2] = fma2(uv.x, wf2.x, acc[r][2]);
            acc[r][2] = fma2(uv.y, wf2.y, acc[r][2]);
            acc[r][3] = fma2(uv.x, wf3.x, acc[r][3]);
            acc[r][3] = fma2(uv.y, wf3.y, acc[r][3]);
        }
    }

    float* pp = part + sl * 1280 + bq * 40 + cg * 16 + 2 * cq;
#pragma unroll
    for (int r = 0; r < 4; ++r) {
        float2 a = unpack2(acc[r][0]);
        float2 b = unpack2(acc[r][1]);
        float2 c = unpack2(acc[r][2]);
        float2 d = unpack2(acc[r][3]);
        *(float2*)(pp + 320 * r)     = make_float2(a.x + a.y, b.x + b.y);
        *(float2*)(pp + 320 * r + 8) = make_float2(c.x + c.y, d.x + d.y);
    }
}

// ---------------- fused partial-reduce + sLSTM cell update ----------------
__device__ __forceinline__ float cell_fused(const float* __restrict__ part,
                                            const float* __restrict__ bias,
                                            int be, int je,
                                            float& c, float& m, float& n) {
    float g4[4];
#pragma unroll
    for (int g = 0; g < 4; ++g) {
        const float* p = part + be * 40 + g * 8 + je;
        float s = bias[g * 8 + je];
#pragma unroll
        for (int sl = 0; sl < 8; ++sl) s += p[sl * 1280];
        g4[g] = s;
    }
    float ig = g4[0], fg = g4[1], zg = g4[2], og = g4[3];
    float z  = tanh_fast(zg);
    float o  = __fdividef(1.0f, 1.0f + __expf(-og));
    float mt = fmaxf(fg + m, ig);
    float it = __expf(ig - mt);
    float ft = __expf(fg + m - mt);
    c = ft * c + it * z;
    n = ft * n + it;
    m = mt;
    return o * __fdividef(c, n);
}

// ---------------- main persistent kernel ----------------
__global__ void __launch_bounds__(BLOCK, 1)
slstm_kernel(const float* __restrict__ x,
             const float* __restrict__ Wxh1, const float* __restrict__ bxh1,
             const float* __restrict__ Whh1, const float* __restrict__ bhh1,
             const float* __restrict__ Wxh2, const float* __restrict__ bxh2,
             const float* __restrict__ Whh2, const float* __restrict__ bhh2,
             const float* __restrict__ W1, const float* __restrict__ b1,
             const float* __restrict__ W2, const float* __restrict__ b2,
             const float* __restrict__ W3, const float* __restrict__ b3,
             float* __restrict__ out) {
    extern __shared__ char smem[];
    u64*    wA    = (u64*)(smem + OFF_WA);
    u64*    wB    = (u64*)(smem + OFF_WB);
    u64*    usm   = (u64*)(smem + OFF_U);
    float4* u4f   = (float4*)(smem + OFF_U);
    float*  part  = (float*)(smem + OFF_P);
    float*  biasA = (float*)(smem + OFF_BA);
    float*  biasB = (float*)(smem + OFF_BB);

    const int tid  = threadIdx.x;
    const int warp = tid >> 5, lane = tid & 31;
    const int sl = warp >> 1, cg = warp & 1;
    const int bgroup = blockIdx.x >> 5;   // 0..3  (32 batch rows each)
    const int jgroup = blockIdx.x & 31;   // 0..31 (8 hidden idx each)

    const unsigned base_g   = ld_acq(&bar_flag[bgroup][jgroup][0]);
    const unsigned base_all = ld_acq(&gbar_gen_all);

    // staging mapping: sb = batch row (0..31), sq = 0..15
    const int sb = tid >> 4, sq = tid & 15;
    const int bglobs = bgroup * 32 + sb;
    const float4 zero4 = make_float4(0.f, 0.f, 0.f, 0.f);

    // prefetch x(0) while weights stage
    float4 xv = *(const float4*)(x + (bglobs * T_D + 0) * IN_D + sq * 4);

    // ---- stage weights (phase A k-order = [h1|x]) + biases + zero u h1 rows ----
    {
        float2* wAf = (float2*)wA;
        for (int s = tid; s < 32 * 160; s += BLOCK) {
            int c = s / 160, k2 = s - c * 160;
            int col = (c >> 3) * 256 + jgroup * 8 + (c & 7);
            int k0 = 2 * k2;
            float2 v;
            if (k0 < H_D) v = *(const float2*)(Whh1 + col * H_D + k0);
            else          v = *(const float2*)(Wxh1 + col * IN_D + (k0 - H_D));
            wAf[c * 162 + k2] = v;
        }
        float2* wBf = (float2*)wB;
        for (int s = tid; s < 32 * 256; s += BLOCK) {
            int c = s >> 8, k2 = s & 255;
            int col = (c >> 3) * 256 + jgroup * 8 + (c & 7);
            int k0 = 2 * k2;
            float2 v;
            if (k0 < H_D) v = *(const float2*)(Wxh2 + col * H_D + k0);
            else          v = *(const float2*)(Whh2 + col * H_D + (k0 - H_D));
            wBf[c * 258 + k2] = v;
        }
        // zero u h1 rows (0..63) for t=0
        for (int s = tid; s < 32 * 64; s += BLOCK) {
            int b = s >> 6, q = s & 63;
            u4f[b * U_S2 + q] = zero4;
        }
    }
    if (tid < 32) {
        int col = (tid >> 3) * 256 + jgroup * 8 + (tid & 7);
        biasA[tid] = bxh1[col] + bhh1[col];
        biasB[tid] = bxh2[col] + bhh2[col];
    }

    // per-thread cell state (tid<256)
    float c1 = 0.f, m1 = 0.f, n1 = 0.f;
    float c2 = 0.f, m2 = 0.f, n2 = 0.f;
    const int be = tid >> 3, je = tid & 7;
    const int bglob_e = bgroup * 32 + be;
    const int jglob   = jgroup * 8 + je;

    for (int t = 0; t < T_D; ++t) {
        float*       h1cur = h1_buf[t & 1];
        float*       h2cur = h2_buf[t & 1];
        const float* h2old = h2_buf[(t + 1) & 1];

        // ---- stage A: just write prefetched x into rows 64..79 ----
        // (h1(t-1) already resides in rows 0..63 from last step's stage B)
        u4f[sb * U_S2 + 64 + sq] = xv;
        __syncthreads();

        gemm_tile<20, WA_S2>(wA, usm, part, sl, cg, lane);
        __syncthreads();

        if (tid < 256) {
            float h1v = cell_fused(part, biasA, be, je, c1, m1, n1);
            h1cur[bglob_e * H_D + jglob] = h1v;
        }
        gbar_flags(bgroup, jgroup, warp, lane, base_g + (unsigned)t + 1u);

        // ---- stage B: h1(t) -> rows 0..63, h2(t-1) -> rows 64..127 ----
        // also prefetch x(t+1) (latency hidden under phase B)
        {
            if (t + 1 < T_D)
                xv = *(const float4*)(x + (bglobs * T_D + (t + 1)) * IN_D + sq * 4);
            float4 hv[4], gv[4];
#pragma unroll
            for (int j = 0; j < 4; ++j)
                hv[j] = __ldcg((const float4*)(h1cur + bglobs * H_D + (sq + 16 * j) * 4));
#pragma unroll
            for (int j = 0; j < 4; ++j)
                gv[j] = (t == 0) ? zero4
                      : __ldcg((const float4*)(h2old + bglobs * H_D + (sq + 16 * j) * 4));
#pragma unroll
            for (int j = 0; j < 4; ++j) u4f[sb * U_S2 + sq + 16 * j] = hv[j];
#pragma unroll
            for (int j = 0; j < 4; ++j) u4f[sb * U_S2 + 64 + sq + 16 * j] = gv[j];
        }
        __syncthreads();

        gemm_tile<32, WB_S2>(wB, usm, part, sl, cg, lane);
        __syncthreads();

        if (tid < 256) {
            float h2v = cell_fused(part, biasB, be, je, c2, m2, n2);
            h2cur[bglob_e * H_D + jglob] = h2v;
        }
        // stage A(t+1) writes only rows 64..79 (consumed by gemmB above);
        // h1 rows 0..63 stay valid. Next group barrier orders h2 for stage B(t+1).
    }

    // all 128 CTAs must see final h2 before the head MLP
    gbar_all(base_all + 1u);

    // ---- head MLP: one batch row per CTA ----
    {
        const float* h2fin = h2_buf[(T_D - 1) & 1];
        int b = blockIdx.x;
        float* hb = (float*)(smem + OFF_U);
        float* o1 = hb + 256;
        float* o2 = o1 + 128;
        float* pr = o2 + 64;
        for (int i = tid; i < H_D; i += BLOCK) hb[i] = __ldcg(h2fin + b * H_D + i);
        __syncthreads();
        if (tid < 128) {
            const float* w = W1 + tid * H_D;
            float s = b1[tid];
#pragma unroll 4
            for (int k = 0; k < H_D; k += 4) {
                float4 hv = *(const float4*)(hb + k);
                float4 wv = *(const float4*)(w + k);
                s += hv.x * wv.x + hv.y * wv.y + hv.z * wv.z + hv.w * wv.w;
            }
            o1[tid] = fmaxf(s, 0.f);
        }
        __syncthreads();
        if (tid < 64) {
            const float* w = W2 + tid * 128;
            float s = b2[tid];
#pragma unroll 4
            for (int k = 0; k < 128; ++k) s += o1[k] * w[k];
            o2[tid] = fmaxf(s, 0.f);
        }
        __syncthreads();
        if (tid < 64) pr[tid] = o2[tid] * W3[tid];
        __syncthreads();
        if (tid == 0) {
            float s = b3[0];
            for (int k = 0; k < 64; ++k) s += pr[k];
            out[b] = s;
        }
    }
}

extern "C" void kernel_launch(void* const* d_in, const int* in_sizes, int n_in,
                              void* d_out, int out_size) {
    const float* x    = (const float*)d_in[0];
    const float* Wxh1 = (const float*)d_in[1];
    const float* bxh1 = (const float*)d_in[2];
    const float* Whh1 = (const float*)d_in[3];
    const float* bhh1 = (const float*)d_in[4];
    const float* Wxh2 = (const float*)d_in[5];
    const float* bxh2 = (const float*)d_in[6];
    const float* Whh2 = (const float*)d_in[7];
    const float* bhh2 = (const float*)d_in[8];
    const float* W1   = (const float*)d_in[9];
    const float* b1   = (const float*)d_in[10];
    const float* W2   = (const float*)d_in[11];
    const float* b2   = (const float*)d_in[12];
    const float* W3   = (const float*)d_in[13];
    const float* b3   = (const float*)d_in[14];

    cudaFuncSetAttribute(slstm_kernel,
                         cudaFuncAttributeMaxDynamicSharedMemorySize, SMEM_BYTES);
    slstm_kernel<<<GRID, BLOCK, SMEM_BYTES>>>(x, Wxh1, bxh1, Whh1, bhh1,
                                              Wxh2, bxh2, Whh2, bhh2,
                                              W1, b1, W2, b2, W3, b3,
                                              (float*)d_out);
}

// round 12
// speedup vs baseline: 1.6293x; 1.5349x over previous
#include <cuda_runtime.h>
#include <cstdint>
#include <math.h>

#define IN_D  64
#define H_D   256
#define B_D   128
#define T_D   512
#define GRID  128
#define BLOCK 512

typedef unsigned long long u64;

// ---------------- device globals ----------------
__device__ float h1_buf[2][B_D * H_D];
__device__ float h2_buf[2][B_D * H_D];
__device__ unsigned bar_cnt4[4][32];   // monotone arrival counters, one padded line per bgroup
__device__ unsigned gbar_cnt_all;      // monotone chip-wide counter

// ---------------- smem layout ----------------
// wA : [32 c][162 k2] u64 = 41472   (layer1, K=320 -> 160 k-pairs, stride 162 == 2 mod 16)
// wB : [32 c][258 k2] u64 = 66048   (layer2, K=512 -> 256 k-pairs, stride 258)
// u  : [32 b][258 k2] u64 = 66048   (staging, stride 258)
// part:[8 sl][32 b][40 c] f32 = 40960  (stride 40 -> coalesced float2 stores)
// gate:[32][32] f32 = 4096
#define WA_S2 81     /* wA row stride in ulonglong2 units (162/2) */
#define WB_S2 129    /* wB/u row stride in ulonglong2 units (258/2) */
#define OFF_WA 0
#define OFF_WB 41472
#define OFF_U  107520
#define OFF_P  173568
#define OFF_G  214528
#define OFF_BA 218624
#define OFF_BB 218752
#define SMEM_BYTES 218880

// ---------------- asm helpers ----------------
__device__ __forceinline__ unsigned ld_acq(const unsigned* p) {
    unsigned v;
    asm volatile("ld.acquire.gpu.u32 %0, [%1];" : "=r"(v) : "l"(p) : "memory");
    return v;
}
__device__ __forceinline__ void red_rel_add1(unsigned* p) {
    asm volatile("red.release.gpu.global.add.u32 [%0], 1;" :: "l"(p) : "memory");
}
__device__ __forceinline__ u64 fma2(u64 a, u64 b, u64 c) {
    u64 d;
    asm("fma.rn.f32x2 %0, %1, %2, %3;" : "=l"(d) : "l"(a), "l"(b), "l"(c));
    return d;
}
__device__ __forceinline__ float2 unpack2(u64 v) {
    float2 r; asm("mov.b64 {%0,%1}, %2;" : "=f"(r.x), "=f"(r.y) : "l"(v)); return r;
}
__device__ __forceinline__ float tanh_fast(float x) {
    float r;
    asm("tanh.approx.f32 %0, %1;" : "=f"(r) : "f"(x));
    return r;
}

// ---------------- grid barrier: monotone RED arrival + poll (no reset) ----------------
__device__ __forceinline__ void gbar_red(unsigned* cnt, unsigned target) {
    __syncthreads();
    if (threadIdx.x == 0) {
        red_rel_add1(cnt);
        while ((int)(ld_acq(cnt) - target) < 0) { }
    }
    __syncthreads();
}

// ---------------- register-tiled GEMM ----------------
// 16 warps = 8 k-slices x 2 c-halves. Lanes (bq 0..7, cq 0..3).
// Thread tile 4b x 4c: b in {bq+8r}, c in {cg*16 + 2cq + {0,1,8,9}}.
// u[b][k2] stride 258 u64; w[c][k2] stride 2*WS2 u64. k-pairs packed in f32x2.
template<int K2S, int WS2>
__device__ __forceinline__ void gemm_tile(const u64* __restrict__ wsm,
                                          const u64* __restrict__ usm,
                                          float* __restrict__ part,
                                          int sl, int cg, int lane) {
    const int bq = lane & 7, cq = (lane >> 3) & 3;
    const int k2h = (sl * K2S) >> 1;   // slice base in ulonglong2 units
    const ulonglong2* up = (const ulonglong2*)usm + bq * WB_S2 + k2h;
    const ulonglong2* wp = (const ulonglong2*)wsm + (cg * 16 + 2 * cq) * WS2 + k2h;

    u64 acc[4][4];
#pragma unroll
    for (int r = 0; r < 4; ++r)
#pragma unroll
        for (int j = 0; j < 4; ++j) acc[r][j] = 0;

#pragma unroll 2
    for (int k = 0; k < K2S / 2; ++k) {
        ulonglong2 uf0 = up[k];
        ulonglong2 uf1 = up[k +  8 * WB_S2];
        ulonglong2 uf2 = up[k + 16 * WB_S2];
        ulonglong2 uf3 = up[k + 24 * WB_S2];
        ulonglong2 wf0 = wp[k];
        ulonglong2 wf1 = wp[k + WS2];
        ulonglong2 wf2 = wp[k + 8 * WS2];
        ulonglong2 wf3 = wp[k + 9 * WS2];
#pragma unroll
        for (int r = 0; r < 4; ++r) {
            ulonglong2 uv = (r == 0) ? uf0 : (r == 1) ? uf1 : (r == 2) ? uf2 : uf3;
            acc[r][0] = fma2(uv.x, wf0.x, acc[r][0]);
            acc[r][0] = fma2(uv.y, wf0.y, acc[r][0]);
            acc[r][1] = fma2(uv.x, wf1.x, acc[r][1]);
            acc[r][1] = fma2(uv.y, wf1.y, acc[r][1]);
            acc[r][2] = fma2(uv.x, wf2.x, acc[r][2]);
            acc[r][2] = fma2(uv.y, wf2.y, acc[r][2]);
            acc[r][3] = fma2(uv.x, wf3.x, acc[r][3]);
            acc[r][3] = fma2(uv.y, wf3.y, acc[r][3]);
        }
    }

    float* pp = part + sl * 1280 + bq * 40 + cg * 16 + 2 * cq;
#pragma unroll
    for (int r = 0; r < 4; ++r) {
        float2 a = unpack2(acc[r][0]);
        float2 b = unpack2(acc[r][1]);
        float2 c = unpack2(acc[r][2]);
        float2 d = unpack2(acc[r][3]);
        *(float2*)(pp + 320 * r)     = make_float2(a.x + a.y, b.x + b.y);
        *(float2*)(pp + 320 * r + 8) = make_float2(c.x + c.y, d.x + d.y);
    }
}

// reduce 8 slice-partials + bias -> gate[b][c]
__device__ __forceinline__ void reduce_gate(const float* __restrict__ part,
                                            const float* __restrict__ bias,
                                            float* __restrict__ gate, int tid) {
#pragma unroll
    for (int e = tid; e < 1024; e += BLOCK) {
        int b = e >> 5, c = e & 31;
        const float* p = part + b * 40 + c;
        float s = bias[c];
#pragma unroll
        for (int sl = 0; sl < 8; ++sl) s += p[sl * 1280];
        gate[b * 32 + c] = s;
    }
}

// ---------------- sLSTM cell elementwise update ----------------
__device__ __forceinline__ float cell_update(const float* __restrict__ gate,
                                             int be, int je,
                                             float& c, float& m, float& n) {
    float ig = gate[be * 32 +      je];
    float fg = gate[be * 32 +  8 + je];
    float zg = gate[be * 32 + 16 + je];
    float og = gate[be * 32 + 24 + je];
    float z  = tanh_fast(zg);
    float o  = __fdividef(1.0f, 1.0f + __expf(-og));
    float mt = fmaxf(fg + m, ig);
    float it = __expf(ig - mt);
    float ft = __expf(fg + m - mt);
    c = ft * c + it * z;
    n = ft * n + it;
    m = mt;
    return o * __fdividef(c, n);
}

// ---------------- main persistent kernel ----------------
__global__ void __launch_bounds__(BLOCK, 1)
slstm_kernel(const float* __restrict__ x,
             const float* __restrict__ Wxh1, const float* __restrict__ bxh1,
             const float* __restrict__ Whh1, const float* __restrict__ bhh1,
             const float* __restrict__ Wxh2, const float* __restrict__ bxh2,
             const float* __restrict__ Whh2, const float* __restrict__ bhh2,
             const float* __restrict__ W1, const float* __restrict__ b1,
             const float* __restrict__ W2, const float* __restrict__ b2,
             const float* __restrict__ W3, const float* __restrict__ b3,
             float* __restrict__ out) {
    extern __shared__ char smem[];
    u64*    wA    = (u64*)(smem + OFF_WA);
    u64*    wB    = (u64*)(smem + OFF_WB);
    u64*    usm   = (u64*)(smem + OFF_U);
    float4* u4f   = (float4*)(smem + OFF_U);
    float*  part  = (float*)(smem + OFF_P);
    float*  gate  = (float*)(smem + OFF_G);
    float*  biasA = (float*)(smem + OFF_BA);
    float*  biasB = (float*)(smem + OFF_BB);

    const int tid  = threadIdx.x;
    const int warp = tid >> 5, lane = tid & 31;
    const int sl = warp >> 1, cg = warp & 1;
    const int bgroup = blockIdx.x >> 5;   // 0..3  (32 batch rows each)
    const int jgroup = blockIdx.x & 31;   // 0..31 (8 hidden idx each)

    unsigned* my_cnt = &bar_cnt4[bgroup][0];
    const unsigned base_g   = ld_acq(my_cnt);        // stable across graph replays
    const unsigned base_all = ld_acq(&gbar_cnt_all);

    // staging: sb = batch row (0..31), sq = 0..15; u row = sb*129 float4
    const int sb = tid >> 4, sq = tid & 15;
    const int bglobs = bgroup * 32 + sb;
    const float4 zero4 = make_float4(0.f, 0.f, 0.f, 0.f);

    // prefetch x(0) while weights stage
    float4 xv = *(const float4*)(x + (bglobs * T_D + 0) * IN_D + sq * 4);

    // ---- stage weights (k-pair rows per column) + biases ----
    // smem col c: gate g = c>>3, jl = c&7 -> global gate row = g*256 + jgroup*8 + jl
    {
        float2* wAf = (float2*)wA;
        for (int s = tid; s < 32 * 160; s += BLOCK) {
            int c = s / 160, k2 = s - c * 160;
            int col = (c >> 3) * 256 + jgroup * 8 + (c & 7);
            int k0 = 2 * k2;
            float2 v;
            if (k0 < IN_D) v = *(const float2*)(Wxh1 + col * IN_D + k0);
            else           v = *(const float2*)(Whh1 + col * H_D + (k0 - IN_D));
            wAf[c * 162 + k2] = v;
        }
        float2* wBf = (float2*)wB;
        for (int s = tid; s < 32 * 256; s += BLOCK) {
            int c = s >> 8, k2 = s & 255;
            int col = (c >> 3) * 256 + jgroup * 8 + (c & 7);
            int k0 = 2 * k2;
            float2 v;
            if (k0 < H_D) v = *(const float2*)(Wxh2 + col * H_D + k0);
            else          v = *(const float2*)(Whh2 + col * H_D + (k0 - H_D));
            wBf[c * 258 + k2] = v;
        }
    }
    if (tid < 32) {
        int col = (tid >> 3) * 256 + jgroup * 8 + (tid & 7);
        biasA[tid] = bxh1[col] + bhh1[col];
        biasB[tid] = bxh2[col] + bhh2[col];
    }
    __syncthreads();

    // per-thread cell state (tid<256)
    float c1 = 0.f, m1 = 0.f, n1 = 0.f;
    float c2 = 0.f, m2 = 0.f, n2 = 0.f;
    const int be = tid >> 3, je = tid & 7;
    const int bglob_e = bgroup * 32 + be;
    const int jglob   = jgroup * 8 + je;

    for (int t = 0; t < T_D; ++t) {
        float*       h1cur = h1_buf[t & 1];
        const float* h1old = h1_buf[(t + 1) & 1];
        float*       h2cur = h2_buf[t & 1];
        const float* h2old = h2_buf[(t + 1) & 1];

        // ---- stage u = [x_t | h1_old]  (80 float4 per b); x from register prefetch ----
        {
            u4f[sb * 129 + sq] = xv;
#pragma unroll
            for (int i = 1; i < 5; ++i) {
                int q = sq + 16 * i;
                float4 v = (t == 0) ? zero4
                         : __ldcg((const float4*)(h1old + bglobs * H_D + (q - 16) * 4));
                u4f[sb * 129 + q] = v;
            }
        }
        __syncthreads();

        gemm_tile<20, WA_S2>(wA, usm, part, sl, cg, lane);
        __syncthreads();
        reduce_gate(part, biasA, gate, tid);
        __syncthreads();

        if (tid < 256) {
            float h1v = cell_update(gate, be, je, c1, m1, n1);
            h1cur[bglob_e * H_D + jglob] = h1v;
        }
        gbar_red(my_cnt, base_g + 32u * ((unsigned)t + 1u));   // one barrier per step

        // ---- stage u = [h1_cur | h2_old]  (128 float4 per b); prefetch x(t+1) first ----
        {
            if (t + 1 < T_D)
                xv = *(const float4*)(x + (bglobs * T_D + (t + 1)) * IN_D + sq * 4);
#pragma unroll
            for (int i = 0; i < 4; ++i) {
                int q = sq + 16 * i;
                float4 v = __ldcg((const float4*)(h1cur + bglobs * H_D + q * 4));
                u4f[sb * 129 + q] = v;
            }
#pragma unroll
            for (int i = 4; i < 8; ++i) {
                int q = sq + 16 * i;
                float4 v = (t == 0) ? zero4
                         : __ldcg((const float4*)(h2old + bglobs * H_D + (q - 64) * 4));
                u4f[sb * 129 + q] = v;
            }
        }
        __syncthreads();

        gemm_tile<32, WB_S2>(wB, usm, part, sl, cg, lane);
        __syncthreads();
        reduce_gate(part, biasB, gate, tid);
        __syncthreads();

        if (tid < 256) {
            float h2v = cell_update(gate, be, je, c2, m2, n2);
            h2cur[bglob_e * H_D + jglob] = h2v;
        }
        // next step's group barrier provides the h2 ordering
    }

    // all 128 CTAs must see final h2 before the head MLP
    gbar_red(&gbar_cnt_all, base_all + (unsigned)GRID);

    // ---- head MLP: one batch row per CTA ----
    {
        const float* h2fin = h2_buf[(T_D - 1) & 1];
        int b = blockIdx.x;
        float* hb = (float*)(smem + OFF_U);
        float* o1 = hb + 256;
        float* o2 = o1 + 128;
        float* pr = o2 + 64;
        for (int i = tid; i < H_D; i += BLOCK) hb[i] = __ldcg(h2fin + b * H_D + i);
        __syncthreads();
        if (tid < 128) {
            const float* w = W1 + tid * H_D;
            float s = b1[tid];
#pragma unroll 4
            for (int k = 0; k < H_D; k += 4) {
                float4 hv = *(const float4*)(hb + k);
                float4 wv = *(const float4*)(w + k);
                s += hv.x * wv.x + hv.y * wv.y + hv.z * wv.z + hv.w * wv.w;
            }
            o1[tid] = fmaxf(s, 0.f);
        }
        __syncthreads();
        if (tid < 64) {
            const float* w = W2 + tid * 128;
            float s = b2[tid];
#pragma unroll 4
            for (int k = 0; k < 128; ++k) s += o1[k] * w[k];
            o2[tid] = fmaxf(s, 0.f);
        }
        __syncthreads();
        if (tid < 64) pr[tid] = o2[tid] * W3[tid];
        __syncthreads();
        if (tid == 0) {
            float s = b3[0];
            for (int k = 0; k < 64; ++k) s += pr[k];
            out[b] = s;
        }
    }
}

extern "C" void kernel_launch(void* const* d_in, const int* in_sizes, int n_in,
                              void* d_out, int out_size) {
    const float* x    = (const float*)d_in[0];
    const float* Wxh1 = (const float*)d_in[1];
    const float* bxh1 = (const float*)d_in[2];
    const float* Whh1 = (const float*)d_in[3];
    const float* bhh1 = (const float*)d_in[4];
    const float* Wxh2 = (const float*)d_in[5];
    const float* bxh2 = (const float*)d_in[6];
    const float* Whh2 = (const float*)d_in[7];
    const float* bhh2 = (const float*)d_in[8];
    const float* W1   = (const float*)d_in[9];
    const float* b1   = (const float*)d_in[10];
    const float* W2   = (const float*)d_in[11];
    const float* b2   = (const float*)d_in[12];
    const float* W3   = (const float*)d_in[13];
    const float* b3   = (const float*)d_in[14];

    cudaFuncSetAttribute(slstm_kernel,
                         cudaFuncAttributeMaxDynamicSharedMemorySize, SMEM_BYTES);
    slstm_kernel<<<GRID, BLOCK, SMEM_BYTES>>>(x, Wxh1, bxh1, Whh1, bhh1,
                                              Wxh2, bxh2, Whh2, bhh2,
                                              W1, b1, W2, b2, W3, b3,
                                              (float*)d_out);
}

// round 14
// speedup vs baseline: 1.6957x; 1.0408x over previous
#include <cuda_runtime.h>
#include <cstdint>
#include <math.h>

#define IN_D  64
#define H_D   256
#define B_D   128
#define T_D   512
#define GRID  128
#define BLOCK 512

typedef unsigned long long u64;

// ---------------- device globals ----------------
__device__ float h1_buf[2][B_D * H_D];
__device__ float h2_buf[2][B_D * H_D];
__device__ unsigned bar_cnt4[4][32];   // monotone arrival counters, one padded line per bgroup
__device__ unsigned gbar_cnt_all;      // monotone chip-wide counter

// ---------------- smem layout ----------------
// wA : [32 c][162 k2] u64 = 41472   (layer1, K=320, k-order = [h1(256)|x(64)])
// wB : [32 c][258 k2] u64 = 66048   (layer2, K=512, k-order = [h1(256)|h2(256)])
// u  : [32 b][258 k2] u64 = 66048   rows(f4) 0..63 h1 (persist from stage B),
//                                   64..79 x (phase A) / 64..127 h2 (phase B)
// part:[8 sl][32 b][40 c] f32 = 40960
// gate:[32][32] f32 = 4096
#define WA_S2 81     /* wA row stride in ulonglong2 units (162/2) */
#define WB_S2 129    /* wB/u row stride in ulonglong2 units (258/2) */
#define OFF_WA 0
#define OFF_WB 41472
#define OFF_U  107520
#define OFF_P  173568
#define OFF_G  214528
#define OFF_BA 218624
#define OFF_BB 218752
#define SMEM_BYTES 218880

// ---------------- asm helpers ----------------
__device__ __forceinline__ unsigned ld_acq(const unsigned* p) {
    unsigned v;
    asm volatile("ld.acquire.gpu.u32 %0, [%1];" : "=r"(v) : "l"(p) : "memory");
    return v;
}
__device__ __forceinline__ void red_rel_add1(unsigned* p) {
    asm volatile("red.release.gpu.global.add.u32 [%0], 1;" :: "l"(p) : "memory");
}
__device__ __forceinline__ u64 fma2(u64 a, u64 b, u64 c) {
    u64 d;
    asm("fma.rn.f32x2 %0, %1, %2, %3;" : "=l"(d) : "l"(a), "l"(b), "l"(c));
    return d;
}
__device__ __forceinline__ float2 unpack2(u64 v) {
    float2 r; asm("mov.b64 {%0,%1}, %2;" : "=f"(r.x), "=f"(r.y) : "l"(v)); return r;
}
__device__ __forceinline__ float tanh_fast(float x) {
    float r;
    asm("tanh.approx.f32 %0, %1;" : "=f"(r) : "f"(x));
    return r;
}

// ---------------- grid barrier: monotone RED arrival + poll (no reset) ----------------
__device__ __forceinline__ void gbar_red(unsigned* cnt, unsigned target) {
    __syncthreads();
    if (threadIdx.x == 0) {
        red_rel_add1(cnt);
        while ((int)(ld_acq(cnt) - target) < 0) { }
    }
    __syncthreads();
}

// ---------------- register-tiled GEMM ----------------
// 16 warps = 8 k-slices x 2 c-halves. Lanes (bq 0..7, cq 0..3).
// Thread tile 4b x 4c: b in {bq+8r}, c in {cg*16 + 2cq + {0,1,8,9}}.
// u[b][k2] stride 258 u64; w[c][k2] stride 2*WS2 u64. k-pairs packed in f32x2.
template<int K2S, int WS2>
__device__ __forceinline__ void gemm_tile(const u64* __restrict__ wsm,
                                          const u64* __restrict__ usm,
                                          float* __restrict__ part,
                                          int sl, int cg, int lane) {
    const int bq = lane & 7, cq = (lane >> 3) & 3;
    const int k2h = (sl * K2S) >> 1;   // slice base in ulonglong2 units
    const ulonglong2* up = (const ulonglong2*)usm + bq * WB_S2 + k2h;
    const ulonglong2* wp = (const ulonglong2*)wsm + (cg * 16 + 2 * cq) * WS2 + k2h;

    u64 acc[4][4];
#pragma unroll
    for (int r = 0; r < 4; ++r)
#pragma unroll
        for (int j = 0; j < 4; ++j) acc[r][j] = 0;

#pragma unroll 2
    for (int k = 0; k < K2S / 2; ++k) {
        ulonglong2 uf0 = up[k];
        ulonglong2 uf1 = up[k +  8 * WB_S2];
        ulonglong2 uf2 = up[k + 16 * WB_S2];
        ulonglong2 uf3 = up[k + 24 * WB_S2];
        ulonglong2 wf0 = wp[k];
        ulonglong2 wf1 = wp[k + WS2];
        ulonglong2 wf2 = wp[k + 8 * WS2];
        ulonglong2 wf3 = wp[k + 9 * WS2];
#pragma unroll
        for (int r = 0; r < 4; ++r) {
            ulonglong2 uv = (r == 0) ? uf0 : (r == 1) ? uf1 : (r == 2) ? uf2 : uf3;
            acc[r][0] = fma2(uv.x, wf0.x, acc[r][0]);
            acc[r][0] = fma2(uv.y, wf0.y, acc[r][0]);
            acc[r][1] = fma2(uv.x, wf1.x, acc[r][1]);
            acc[r][1] = fma2(uv.y, wf1.y, acc[r][1]);
            acc[r][2] = fma2(uv.x, wf2.x, acc[r][2]);
            acc[r][2] = fma2(uv.y, wf2.y, acc[r][2]);
            acc[r][3] = fma2(uv.x, wf3.x, acc[r][3]);
            acc[r][3] = fma2(uv.y, wf3.y, acc[r][3]);
        }
    }

    float* pp = part + sl * 1280 + bq * 40 + cg * 16 + 2 * cq;
#pragma unroll
    for (int r = 0; r < 4; ++r) {
        float2 a = unpack2(acc[r][0]);
        float2 b = unpack2(acc[r][1]);
        float2 c = unpack2(acc[r][2]);
        float2 d = unpack2(acc[r][3]);
        *(float2*)(pp + 320 * r)     = make_float2(a.x + a.y, b.x + b.y);
        *(float2*)(pp + 320 * r + 8) = make_float2(c.x + c.y, d.x + d.y);
    }
}

// reduce 8 slice-partials + bias -> gate[b][c]
__device__ __forceinline__ void reduce_gate(const float* __restrict__ part,
                                            const float* __restrict__ bias,
                                            float* __restrict__ gate, int tid) {
#pragma unroll
    for (int e = tid; e < 1024; e += BLOCK) {
        int b = e >> 5, c = e & 31;
        const float* p = part + b * 40 + c;
        float s = bias[c];
#pragma unroll
        for (int sl = 0; sl < 8; ++sl) s += p[sl * 1280];
        gate[b * 32 + c] = s;
    }
}

// ---------------- sLSTM cell elementwise update ----------------
__device__ __forceinline__ float cell_update(const float* __restrict__ gate,
                                             int be, int je,
                                             float& c, float& m, float& n) {
    float ig = gate[be * 32 +      je];
    float fg = gate[be * 32 +  8 + je];
    float zg = gate[be * 32 + 16 + je];
    float og = gate[be * 32 + 24 + je];
    float z  = tanh_fast(zg);
    float o  = __fdividef(1.0f, 1.0f + __expf(-og));
    float mt = fmaxf(fg + m, ig);
    float it = __expf(ig - mt);
    float ft = __expf(fg + m - mt);
    c = ft * c + it * z;
    n = ft * n + it;
    m = mt;
    return o * __fdividef(c, n);
}

// ---------------- main persistent kernel ----------------
__global__ void __launch_bounds__(BLOCK, 1)
slstm_kernel(const float* __restrict__ x,
             const float* __restrict__ Wxh1, const float* __restrict__ bxh1,
             const float* __restrict__ Whh1, const float* __restrict__ bhh1,
             const float* __restrict__ Wxh2, const float* __restrict__ bxh2,
             const float* __restrict__ Whh2, const float* __restrict__ bhh2,
             const float* __restrict__ W1, const float* __restrict__ b1,
             const float* __restrict__ W2, const float* __restrict__ b2,
             const float* __restrict__ W3, const float* __restrict__ b3,
             float* __restrict__ out) {
    extern __shared__ char smem[];
    u64*    wA    = (u64*)(smem + OFF_WA);
    u64*    wB    = (u64*)(smem + OFF_WB);
    u64*    usm   = (u64*)(smem + OFF_U);
    float4* u4f   = (float4*)(smem + OFF_U);
    float*  part  = (float*)(smem + OFF_P);
    float*  gate  = (float*)(smem + OFF_G);
    float*  biasA = (float*)(smem + OFF_BA);
    float*  biasB = (float*)(smem + OFF_BB);

    const int tid  = threadIdx.x;
    const int warp = tid >> 5, lane = tid & 31;
    const int sl = warp >> 1, cg = warp & 1;
    const int bgroup = blockIdx.x >> 5;   // 0..3  (32 batch rows each)
    const int jgroup = blockIdx.x & 31;   // 0..31 (8 hidden idx each)

    unsigned* my_cnt = &bar_cnt4[bgroup][0];
    const unsigned base_g   = ld_acq(my_cnt);        // stable across graph replays
    const unsigned base_all = ld_acq(&gbar_cnt_all);

    // staging: sb = batch row (0..31), sq = 0..15; u row = sb*129 float4
    const int sb = tid >> 4, sq = tid & 15;
    const int bglobs = bgroup * 32 + sb;
    const float4 zero4 = make_float4(0.f, 0.f, 0.f, 0.f);

    // prefetch x(0) while weights stage
    float4 xv = *(const float4*)(x + (bglobs * T_D + 0) * IN_D + sq * 4);

    // ---- stage weights + biases; zero u h1 rows for t=0 ----
    // smem col c: gate g = c>>3, jl = c&7 -> global gate row = g*256 + jgroup*8 + jl
    // wA k-order: k2 0..127 -> Whh1 (h1 contribution), k2 128..159 -> Wxh1 (x)
    {
        float2* wAf = (float2*)wA;
        for (int s = tid; s < 32 * 160; s += BLOCK) {
            int c = s / 160, k2 = s - c * 160;
            int col = (c >> 3) * 256 + jgroup * 8 + (c & 7);
            int k0 = 2 * k2;
            float2 v;
            if (k0 < H_D) v = *(const float2*)(Whh1 + col * H_D + k0);
            else          v = *(const float2*)(Wxh1 + col * IN_D + (k0 - H_D));
            wAf[c * 162 + k2] = v;
        }
        float2* wBf = (float2*)wB;
        for (int s = tid; s < 32 * 256; s += BLOCK) {
            int c = s >> 8, k2 = s & 255;
            int col = (c >> 3) * 256 + jgroup * 8 + (c & 7);
            int k0 = 2 * k2;
            float2 v;
            if (k0 < H_D) v = *(const float2*)(Wxh2 + col * H_D + k0);
            else          v = *(const float2*)(Whh2 + col * H_D + (k0 - H_D));
            wBf[c * 258 + k2] = v;
        }
        // zero u h1 rows (f4 0..63) for t=0
        for (int s = tid; s < 32 * 64; s += BLOCK) {
            int b = s >> 6, q = s & 63;
            u4f[b * 129 + q] = zero4;
        }
    }
    if (tid < 32) {
        int col = (tid >> 3) * 256 + jgroup * 8 + (tid & 7);
        biasA[tid] = bxh1[col] + bhh1[col];
        biasB[tid] = bxh2[col] + bhh2[col];
    }
    __syncthreads();

    // per-thread cell state (tid<256)
    float c1 = 0.f, m1 = 0.f, n1 = 0.f;
    float c2 = 0.f, m2 = 0.f, n2 = 0.f;
    const int be = tid >> 3, je = tid & 7;
    const int bglob_e = bgroup * 32 + be;
    const int jglob   = jgroup * 8 + je;

    for (int t = 0; t < T_D; ++t) {
        float*       h1cur = h1_buf[t & 1];
        float*       h2cur = h2_buf[t & 1];
        const float* h2old = h2_buf[(t + 1) & 1];

        // ---- stage A: write prefetched x into rows 64..79 ----
        // (h1(t-1) persists in rows 0..63 from last step's stage B; zeroed for t=0)
        u4f[sb * 129 + 64 + sq] = xv;
        __syncthreads();

        gemm_tile<20, WA_S2>(wA, usm, part, sl, cg, lane);
        __syncthreads();
        reduce_gate(part, biasA, gate, tid);
        __syncthreads();

        if (tid < 256) {
            float h1v = cell_update(gate, be, je, c1, m1, n1);
            h1cur[bglob_e * H_D + jglob] = h1v;
        }
        gbar_red(my_cnt, base_g + 32u * ((unsigned)t + 1u));   // one barrier per step

        // ---- stage B: h1(t) -> rows 0..63, h2(t-1) -> rows 64..127 ----
        // prefetch x(t+1) first (latency hidden under phase B)
        {
            if (t + 1 < T_D)
                xv = *(const float4*)(x + (bglobs * T_D + (t + 1)) * IN_D + sq * 4);
#pragma unroll
            for (int i = 0; i < 4; ++i) {
                int q = sq + 16 * i;
                float4 v = __ldcg((const float4*)(h1cur + bglobs * H_D + q * 4));
                u4f[sb * 129 + q] = v;
            }
#pragma unroll
            for (int i = 4; i < 8; ++i) {
                int q = sq + 16 * i;
                float4 v = (t == 0) ? zero4
                         : __ldcg((const float4*)(h2old + bglobs * H_D + (q - 64) * 4));
                u4f[sb * 129 + q] = v;
            }
        }
        __syncthreads();

        gemm_tile<32, WB_S2>(wB, usm, part, sl, cg, lane);
        __syncthreads();
        reduce_gate(part, biasB, gate, tid);
        __syncthreads();

        if (tid < 256) {
            float h2v = cell_update(gate, be, je, c2, m2, n2);
            h2cur[bglob_e * H_D + jglob] = h2v;
        }
        // stage A(t+1) touches only rows 64..79 (h2 region read by gemmB, ordered
        // by the post-gemmB sync); h1 rows 0..63 persist into gemmA(t+1).
    }

    // all 128 CTAs must see final h2 before the head MLP
    gbar_red(&gbar_cnt_all, base_all + (unsigned)GRID);

    // ---- head MLP: one batch row per CTA ----
    {
        const float* h2fin = h2_buf[(T_D - 1) & 1];
        int b = blockIdx.x;
        float* hb = (float*)(smem + OFF_U);
        float* o1 = hb + 256;
        float* o2 = o1 + 128;
        float* pr = o2 + 64;
        for (int i = tid; i < H_D; i += BLOCK) hb[i] = __ldcg(h2fin + b * H_D + i);
        __syncthreads();
        if (tid < 128) {
            const float* w = W1 + tid * H_D;
            float s = b1[tid];
#pragma unroll 4
            for (int k = 0; k < H_D; k += 4) {
                float4 hv = *(const float4*)(hb + k);
                float4 wv = *(const float4*)(w + k);
                s += hv.x * wv.x + hv.y * wv.y + hv.z * wv.z + hv.w * wv.w;
            }
            o1[tid] = fmaxf(s, 0.f);
        }
        __syncthreads();
        if (tid < 64) {
            const float* w = W2 + tid * 128;
            float s = b2[tid];
#pragma unroll 4
            for (int k = 0; k < 128; ++k) s += o1[k] * w[k];
            o2[tid] = fmaxf(s, 0.f);
        }
        __syncthreads();
        if (tid < 64) pr[tid] = o2[tid] * W3[tid];
        __syncthreads();
        if (tid == 0) {
            float s = b3[0];
            for (int k = 0; k < 64; ++k) s += pr[k];
            out[b] = s;
        }
    }
}

extern "C" void kernel_launch(void* const* d_in, const int* in_sizes, int n_in,
                              void* d_out, int out_size) {
    const float* x    = (const float*)d_in[0];
    const float* Wxh1 = (const float*)d_in[1];
    const float* bxh1 = (const float*)d_in[2];
    const float* Whh1 = (const float*)d_in[3];
    const float* bhh1 = (const float*)d_in[4];
    const float* Wxh2 = (const float*)d_in[5];
    const float* bxh2 = (const float*)d_in[6];
    const float* Whh2 = (const float*)d_in[7];
    const float* bhh2 = (const float*)d_in[8];
    const float* W1   = (const float*)d_in[9];
    const float* b1   = (const float*)d_in[10];
    const float* W2   = (const float*)d_in[11];
    const float* b2   = (const float*)d_in[12];
    const float* W3   = (const float*)d_in[13];
    const float* b3   = (const float*)d_in[14];

    cudaFuncSetAttribute(slstm_kernel,
                         cudaFuncAttributeMaxDynamicSharedMemorySize, SMEM_BYTES);
    slstm_kernel<<<GRID, BLOCK, SMEM_BYTES>>>(x, Wxh1, bxh1, Whh1, bhh1,
                                              Wxh2, bxh2, Whh2, bhh2,
                                              W1, b1, W2, b2, W3, b3,
                                              (float*)d_out);
}